// round 4
// baseline (speedup 1.0000x reference)
#include <cuda_runtime.h>
#include <cstdint>
#include <math.h>

#define T_LEN  2048
#define D_EMB  300
#define H_DIM  256
#define G4     1024
#define K_TAGS 48
#define START_TAG 46
#define STOP_TAG  47

// ---------------- scratch (device globals; no allocation) ----------------
__device__ float g_x[T_LEN * D_EMB];        // gathered embeddings [T, D]
__device__ float g_xg[2][T_LEN * G4];       // input projections per dir [T, 4H]
__device__ float g_hs[2][T_LEN * H_DIM];    // hidden states per dir, time-aligned
__device__ float g_feats[T_LEN * K_TAGS];   // emission features [T, K]

// ---------------- f32x2 helpers ----------------
__device__ __forceinline__ unsigned long long pack2(float lo, float hi) {
    unsigned long long r;
    asm("mov.b64 %0, {%1,%2};" : "=l"(r) : "f"(lo), "f"(hi));
    return r;
}
__device__ __forceinline__ void unpack2(unsigned long long v, float& lo, float& hi) {
    asm("mov.b64 {%0,%1}, %2;" : "=f"(lo), "=f"(hi) : "l"(v));
}
__device__ __forceinline__ unsigned long long mul2(unsigned long long a, unsigned long long b) {
    unsigned long long d;
    asm("mul.rn.f32x2 %0, %1, %2;" : "=l"(d) : "l"(a), "l"(b));
    return d;
}
__device__ __forceinline__ unsigned long long fma2(unsigned long long a, unsigned long long b,
                                                   unsigned long long c) {
    unsigned long long d;
    asm("fma.rn.f32x2 %0, %1, %2, %3;" : "=l"(d) : "l"(a), "l"(b), "l"(c));
    return d;
}

// ---------------- 1) embedding gather ----------------
__global__ void gather_kernel(const int* __restrict__ sent,
                              const float* __restrict__ E) {
    int idx = blockIdx.x * blockDim.x + threadIdx.x;
    int total = T_LEN * D_EMB;
    for (; idx < total; idx += gridDim.x * blockDim.x) {
        int t = idx / D_EMB;
        int d = idx - t * D_EMB;
        long long row = sent[t];
        g_x[idx] = E[row * D_EMB + d];
    }
}

// ---------------- 2) xg GEMM: [T,D] @ [4H,D]^T + (b_ih + b_hh) ----------------
#define BM 64
#define BN 64
#define BK 12
__global__ void xg_gemm_kernel(const float* __restrict__ Wf,
                               const float* __restrict__ Wb,
                               const float* __restrict__ bihf,
                               const float* __restrict__ bhhf,
                               const float* __restrict__ bihb,
                               const float* __restrict__ bhhb) {
    int dir = blockIdx.z;
    const float* W  = dir ? Wb   : Wf;
    const float* b1 = dir ? bihb : bihf;
    const float* b2 = dir ? bhhb : bhhf;

    __shared__ float As[BK][BM];
    __shared__ float Bs[BK][BN];

    int t0 = blockIdx.x * BM;
    int r0 = blockIdx.y * BN;
    int tid = threadIdx.x;           // 256 threads
    int tx = tid & 15;
    int ty = tid >> 4;

    float acc[4][4];
#pragma unroll
    for (int i = 0; i < 4; i++)
#pragma unroll
        for (int j = 0; j < 4; j++) acc[i][j] = 0.f;

    for (int k0 = 0; k0 < D_EMB; k0 += BK) {   // 300 = 25 * 12, no guards
#pragma unroll
        for (int l2 = 0; l2 < 3; l2++) {
            int idx = tid + l2 * 256;       // 0..767
            int row = idx / 12;             // 0..63
            int kk  = idx - row * 12;
            int tg = t0 + row;
            int ts = dir ? (T_LEN - 1 - tg) : tg;
            As[kk][row] = g_x[ts * D_EMB + k0 + kk];
            Bs[kk][row] = W[(r0 + row) * D_EMB + k0 + kk];
        }
        __syncthreads();
#pragma unroll
        for (int kk = 0; kk < BK; kk++) {
            float ra[4], rb[4];
#pragma unroll
            for (int i = 0; i < 4; i++) ra[i] = As[kk][ty * 4 + i];
#pragma unroll
            for (int j = 0; j < 4; j++) rb[j] = Bs[kk][tx * 4 + j];
#pragma unroll
            for (int i = 0; i < 4; i++)
#pragma unroll
                for (int j = 0; j < 4; j++) acc[i][j] += ra[i] * rb[j];
        }
        __syncthreads();
    }

#pragma unroll
    for (int i = 0; i < 4; i++) {
        int t = t0 + ty * 4 + i;
#pragma unroll
        for (int j = 0; j < 4; j++) {
            int r = r0 + tx * 4 + j;
            g_xg[dir][t * G4 + r] = acc[i][j] + b1[r] + b2[r];
        }
    }
}

// ---------------- 3a) LSTM recurrence: 8-CTA cluster (fallback) ----------------
// CTA rank owns hidden units [rank*32, rank*32+32). Warp w owns units 2w,2w+1.
// Parallel DSMEM fan-out: lanes 0-7 each store the packed h-pair to one target
// CTA (single warp instruction). Split barrier: arrive right after stores,
// global hs store between arrive and wait.
__global__ void __launch_bounds__(512, 1) __cluster_dims__(8, 1, 1)
lstm_kernel8(const float* __restrict__ Whf, const float* __restrict__ Whb) {
    __shared__ float h_buf[2][H_DIM];

    int dir = blockIdx.y;
    const float* Whh = dir ? Whb : Whf;
    const float* xg = g_xg[dir];
    float* hs = g_hs[dir];

    uint32_t rank;
    asm("mov.u32 %0, %%cluster_ctarank;" : "=r"(rank));

    int tid = threadIdx.x;
    int w = tid >> 5;
    int l = tid & 31;
    int r = l & 7;                 // W row this lane finalizes
    int gate = r & 3;
    int du = r >> 2;
    int xg_col = gate * H_DIM + (int)rank * 32 + 2 * w + du;

    unsigned long long w2[8][4];
#pragma unroll
    for (int q = 0; q < 8; q++) {
        int row = (q & 3) * H_DIM + (int)rank * 32 + 2 * w + (q >> 2);
        const float4* p = (const float4*)(Whh + (size_t)row * H_DIM + l * 8);
        float4 a = p[0];
        float4 b = p[1];
        w2[q][0] = pack2(a.x, a.y); w2[q][1] = pack2(a.z, a.w);
        w2[q][2] = pack2(b.x, b.y); w2[q][3] = pack2(b.z, b.w);
    }

    if (tid < 2 * H_DIM) ((float*)h_buf)[tid] = 0.f;
    uint32_t hb = (uint32_t)__cvta_generic_to_shared(&h_buf[0][0]);

    uint32_t rH[8];
#pragma unroll
    for (int tg = 0; tg < 8; tg++) {
        asm("mapa.shared::cluster.u32 %0, %1, %2;" : "=r"(rH[tg]) : "r"(hb), "r"(tg));
    }

    __syncthreads();
    asm volatile("barrier.cluster.arrive.aligned;" ::: "memory");
    asm volatile("barrier.cluster.wait.aligned;" ::: "memory");

    float c_reg = 0.f;
    float xg_pref = xg[xg_col];
    const float LOG2E = 1.4426950408889634f;

#pragma unroll 1
    for (int t = 0; t < T_LEN; t++) {
        int cur = t & 1;
        int nxt = cur ^ 1;

        float4 ha = *(const float4*)&h_buf[cur][l * 8];
        float4 hc = *(const float4*)&h_buf[cur][l * 8 + 4];
        unsigned long long h2[4] = { pack2(ha.x, ha.y), pack2(ha.z, ha.w),
                                     pack2(hc.x, hc.y), pack2(hc.z, hc.w) };
        float v[8];
#pragma unroll
        for (int q = 0; q < 8; q++) {
            unsigned long long acc = mul2(w2[q][0], h2[0]);
            acc = fma2(w2[q][1], h2[1], acc);
            acc = fma2(w2[q][2], h2[2], acc);
            acc = fma2(w2[q][3], h2[3], acc);
            float lo, hi;
            unpack2(acc, lo, hi);
            v[q] = lo + hi;
        }

#pragma unroll
        for (int i = 0; i < 4; i++) {
            float send = (l & 16) ? v[i] : v[i + 4];
            float recv = __shfl_xor_sync(0xffffffffu, send, 16);
            float keep = (l & 16) ? v[i + 4] : v[i];
            v[i] = keep + recv;
        }
#pragma unroll
        for (int i = 0; i < 2; i++) {
            float send = (l & 8) ? v[i] : v[i + 2];
            float recv = __shfl_xor_sync(0xffffffffu, send, 8);
            float keep = (l & 8) ? v[i + 2] : v[i];
            v[i] = keep + recv;
        }
        {
            float send = (l & 4) ? v[0] : v[1];
            float recv = __shfl_xor_sync(0xffffffffu, send, 4);
            float keep = (l & 4) ? v[1] : v[0];
            v[0] = keep + recv;
        }
        float x = __shfl_sync(0xffffffffu, v[0], ((l & 7) << 2) | ((l >> 3) & 3));
        x += __shfl_xor_sync(0xffffffffu, x, 8);
        x += __shfl_xor_sync(0xffffffffu, x, 16);

        float pre = x + xg_pref;
        if (t + 1 < T_LEN)
            xg_pref = xg[(size_t)(t + 1) * G4 + xg_col];

        float aa = (gate == 2) ? (2.f * LOG2E) : (-LOG2E);
        float e = exp2f(aa * pre);
        float z = __fdividef(1.f, 1.f + e);
        float act = (gate == 2) ? fmaf(-2.f, z, 1.f) : z;

        int base = ((l >> 2) & 1) * 4;
        float iv = __shfl_sync(0xffffffffu, act, base);
        float fv = __shfl_sync(0xffffffffu, act, base + 1);
        float gg = __shfl_sync(0xffffffffu, act, base + 2);
        float ov = __shfl_sync(0xffffffffu, act, base + 3);

        c_reg = fmaf(fv, c_reg, iv * gg);
        float e2 = exp2f(2.f * LOG2E * c_reg);
        float hval = ov * fmaf(-2.f, __fdividef(1.f, 1.f + e2), 1.f);

        // all lanes obtain the warp's h pair; lanes 0-7 fan out (one instr)
        float h0 = __shfl_sync(0xffffffffu, hval, 0);
        float h1 = __shfl_sync(0xffffffffu, hval, 4);
        unsigned long long pk = pack2(h0, h1);
        uint32_t off = (uint32_t)((nxt * H_DIM + (int)rank * 32 + 2 * w) * 4);
        if (l < 8) {
            asm volatile("st.shared::cluster.b64 [%0], %1;"
                         :: "r"(rH[l] + off), "l"(pk) : "memory");
        }

        asm volatile("barrier.cluster.arrive.aligned;" ::: "memory");

        if (l == 0) {
            int tout = dir ? (T_LEN - 1 - t) : t;
            *(float2*)&hs[(size_t)tout * H_DIM + rank * 32 + 2 * w] =
                make_float2(h0, h1);
        }

        asm volatile("barrier.cluster.wait.aligned;" ::: "memory");
    }

    asm volatile("barrier.cluster.arrive.aligned;" ::: "memory");
    asm volatile("barrier.cluster.wait.aligned;" ::: "memory");
}

// ---------------- 3b) LSTM recurrence: 16-CTA cluster (primary) ----------------
// CTA rank owns units [rank*16, rank*16+16). Warp w owns exactly one unit
// u = rank*16 + w (4 gate rows, 32 weight regs/thread). Halves the per-SM
// FMA issue floor vs the 8-CTA version. Lanes 0-15 fan the single h value out
// to all 16 CTAs in one store instruction.
__global__ void __launch_bounds__(512, 1)
lstm_kernel16(const float* __restrict__ Whf, const float* __restrict__ Whb) {
    __shared__ float h_buf[2][H_DIM];

    int dir = blockIdx.y;
    const float* Whh = dir ? Whb : Whf;
    const float* xg = g_xg[dir];
    float* hs = g_hs[dir];

    uint32_t rank;
    asm("mov.u32 %0, %%cluster_ctarank;" : "=r"(rank));

    int tid = threadIdx.x;
    int w = tid >> 5;
    int l = tid & 31;
    int u = (int)rank * 16 + w;    // the unit this warp owns
    int gate = l & 3;
    int xg_col = gate * H_DIM + u;

    // 4 gate rows of W_hh for unit u; lane covers k in [8l, 8l+8)
    unsigned long long w2[4][4];
#pragma unroll
    for (int q = 0; q < 4; q++) {
        int row = q * H_DIM + u;
        const float4* p = (const float4*)(Whh + (size_t)row * H_DIM + l * 8);
        float4 a = p[0];
        float4 b = p[1];
        w2[q][0] = pack2(a.x, a.y); w2[q][1] = pack2(a.z, a.w);
        w2[q][2] = pack2(b.x, b.y); w2[q][3] = pack2(b.z, b.w);
    }

    if (tid < 2 * H_DIM) ((float*)h_buf)[tid] = 0.f;
    uint32_t hb = (uint32_t)__cvta_generic_to_shared(&h_buf[0][0]);

    uint32_t rH[16];
#pragma unroll
    for (int tg = 0; tg < 16; tg++) {
        asm("mapa.shared::cluster.u32 %0, %1, %2;" : "=r"(rH[tg]) : "r"(hb), "r"(tg));
    }

    __syncthreads();
    asm volatile("barrier.cluster.arrive.aligned;" ::: "memory");
    asm volatile("barrier.cluster.wait.aligned;" ::: "memory");

    float c_reg = 0.f;
    float xg_pref = xg[xg_col];
    const float LOG2E = 1.4426950408889634f;

#pragma unroll 1
    for (int t = 0; t < T_LEN; t++) {
        int cur = t & 1;
        int nxt = cur ^ 1;

        float4 ha = *(const float4*)&h_buf[cur][l * 8];
        float4 hc = *(const float4*)&h_buf[cur][l * 8 + 4];
        unsigned long long h2[4] = { pack2(ha.x, ha.y), pack2(ha.z, ha.w),
                                     pack2(hc.x, hc.y), pack2(hc.z, hc.w) };
        float v[4];
#pragma unroll
        for (int q = 0; q < 4; q++) {
            unsigned long long acc = mul2(w2[q][0], h2[0]);
            acc = fma2(w2[q][1], h2[1], acc);
            acc = fma2(w2[q][2], h2[2], acc);
            acc = fma2(w2[q][3], h2[3], acc);
            float lo, hi;
            unpack2(acc, lo, hi);
            v[q] = lo + hi;
        }

        // reduce-scatter over lane bits 4,3: after these, lane holds row
        // rrow = 2*bit4(l) + bit3(l), partial index = l & 7 (8 partials)
#pragma unroll
        for (int i = 0; i < 2; i++) {
            float send = (l & 16) ? v[i] : v[i + 2];
            float recv = __shfl_xor_sync(0xffffffffu, send, 16);
            float keep = (l & 16) ? v[i + 2] : v[i];
            v[i] = keep + recv;
        }
        {
            float send = (l & 8) ? v[0] : v[1];
            float recv = __shfl_xor_sync(0xffffffffu, send, 8);
            float keep = (l & 8) ? v[1] : v[0];
            v[0] = keep + recv;
        }
        // realign: lane l takes row (l&3), partial (l>>2)&7
        float x = __shfl_sync(0xffffffffu, v[0], ((l & 3) << 3) | ((l >> 2) & 7));
        // combine 8 partials (lane bits 2,3,4)
        x += __shfl_xor_sync(0xffffffffu, x, 4);
        x += __shfl_xor_sync(0xffffffffu, x, 8);
        x += __shfl_xor_sync(0xffffffffu, x, 16);

        float pre = x + xg_pref;
        if (t + 1 < T_LEN)
            xg_pref = xg[(size_t)(t + 1) * G4 + xg_col];

        float aa = (gate == 2) ? (2.f * LOG2E) : (-LOG2E);
        float e = exp2f(aa * pre);
        float z = __fdividef(1.f, 1.f + e);
        float act = (gate == 2) ? fmaf(-2.f, z, 1.f) : z;

        float iv = __shfl_sync(0xffffffffu, act, 0);
        float fv = __shfl_sync(0xffffffffu, act, 1);
        float gg = __shfl_sync(0xffffffffu, act, 2);
        float ov = __shfl_sync(0xffffffffu, act, 3);

        c_reg = fmaf(fv, c_reg, iv * gg);
        float e2 = exp2f(2.f * LOG2E * c_reg);
        float hval = ov * fmaf(-2.f, __fdividef(1.f, 1.f + e2), 1.f);
        // hval identical on all lanes of the warp

        uint32_t off = (uint32_t)((nxt * H_DIM + u) * 4);
        if (l < 16) {
            asm volatile("st.shared::cluster.f32 [%0], %1;"
                         :: "r"(rH[l] + off), "f"(hval) : "memory");
        }

        asm volatile("barrier.cluster.arrive.aligned;" ::: "memory");

        if (l == 0) {
            int tout = dir ? (T_LEN - 1 - t) : t;
            hs[(size_t)tout * H_DIM + u] = hval;
        }

        asm volatile("barrier.cluster.wait.aligned;" ::: "memory");
    }

    asm volatile("barrier.cluster.arrive.aligned;" ::: "memory");
    asm volatile("barrier.cluster.wait.aligned;" ::: "memory");
}

// ---------------- 4) feats GEMM: [T,512] @ [48,512]^T + b_out ----------------
#define FT_TT 64
__global__ void feats_gemm_kernel(const float* __restrict__ W_out,
                                  const float* __restrict__ b_out) {
    __shared__ float As[32][FT_TT];   // [j][t]
    __shared__ float Bs[32][K_TAGS];  // [j][k]

    int t0 = blockIdx.x * FT_TT;
    int tid = threadIdx.x;            // 256
    int tx = tid & 15;                // k-group: 3 tags
    int ty = tid >> 4;                // t-group: 4 steps

    float acc[4][3];
#pragma unroll
    for (int i = 0; i < 4; i++)
#pragma unroll
        for (int k = 0; k < 3; k++) acc[i][k] = 0.f;

    for (int j0 = 0; j0 < 2 * H_DIM; j0 += 32) {
#pragma unroll
        for (int i = 0; i < 8; i++) {
            int idx = tid + i * 256;        // 0..2047
            int jj = idx & 31;
            int tt = idx >> 5;
            int j = j0 + jj;
            float hv = (j < H_DIM)
                ? g_hs[0][(size_t)(t0 + tt) * H_DIM + j]
                : g_hs[1][(size_t)(t0 + tt) * H_DIM + (j - H_DIM)];
            As[jj][tt] = hv;
        }
#pragma unroll
        for (int i = 0; i < 6; i++) {
            int idx = tid + i * 256;        // 0..1535
            int k = idx % K_TAGS;
            int jj = idx / K_TAGS;
            Bs[jj][k] = W_out[(size_t)k * (2 * H_DIM) + j0 + jj];
        }
        __syncthreads();
#pragma unroll
        for (int jj = 0; jj < 32; jj++) {
            float a[4], b[3];
#pragma unroll
            for (int i = 0; i < 4; i++) a[i] = As[jj][ty * 4 + i];
#pragma unroll
            for (int k = 0; k < 3; k++) b[k] = Bs[jj][tx * 3 + k];
#pragma unroll
            for (int i = 0; i < 4; i++)
#pragma unroll
                for (int k = 0; k < 3; k++) acc[i][k] += a[i] * b[k];
        }
        __syncthreads();
    }

#pragma unroll
    for (int i = 0; i < 4; i++) {
        int t = t0 + ty * 4 + i;
#pragma unroll
        for (int k = 0; k < 3; k++) {
            int kk = tx * 3 + k;
            g_feats[t * K_TAGS + kk] = acc[i][k] + b_out[kk];
        }
    }
}

// ---------------- 5) Viterbi + backtrace (single CTA, bptrs in SMEM) ----------------
#define VIT_SMEM (T_LEN * K_TAGS + 2 * K_TAGS * 4 + 16)
extern __shared__ unsigned char vit_smem[];
__global__ void viterbi_kernel(const float* __restrict__ trans,
                               float* __restrict__ out) {
    unsigned char* bptr = vit_smem;                       // [T][48] u8 = 96KB
    float* fv = (float*)(vit_smem + T_LEN * K_TAGS);      // [2][48]
    int tid = threadIdx.x;  // 64

    float tr[K_TAGS];
    float featp = 0.f;
    if (tid < K_TAGS) {
#pragma unroll
        for (int j = 0; j < K_TAGS; j++) tr[j] = trans[tid * K_TAGS + j];
        fv[tid] = (tid == START_TAG) ? 0.f : -10000.f;
        featp = g_feats[tid];
    }
    __syncthreads();

    for (int t = 0; t < T_LEN; t++) {
        int cur = (t & 1) * K_TAGS;
        int nxt = K_TAGS - cur;
        if (tid < K_TAGS) {
            float feat = featp;
            if (t + 1 < T_LEN) featp = g_feats[(t + 1) * K_TAGS + tid];
            float b0 = -3.4e38f, b1 = -3.4e38f, b2 = -3.4e38f, b3 = -3.4e38f;
            int a0 = 0, a1 = 1, a2 = 2, a3 = 3;
#pragma unroll
            for (int j = 0; j < K_TAGS; j += 4) {
                float s0 = fv[cur + j]     + tr[j];
                float s1 = fv[cur + j + 1] + tr[j + 1];
                float s2 = fv[cur + j + 2] + tr[j + 2];
                float s3 = fv[cur + j + 3] + tr[j + 3];
                if (s0 > b0) { b0 = s0; a0 = j; }
                if (s1 > b1) { b1 = s1; a1 = j + 1; }
                if (s2 > b2) { b2 = s2; a2 = j + 2; }
                if (s3 > b3) { b3 = s3; a3 = j + 3; }
            }
            float bv = b0; int ba = a0;
            if (b1 > bv || (b1 == bv && a1 < ba)) { bv = b1; ba = a1; }
            if (b2 > bv || (b2 == bv && a2 < ba)) { bv = b2; ba = a2; }
            if (b3 > bv || (b3 == bv && a3 < ba)) { bv = b3; ba = a3; }
            fv[nxt + tid] = bv + feat;
            bptr[t * K_TAGS + tid] = (unsigned char)ba;
        }
        __syncthreads();
    }

    if (tid == STOP_TAG) {
        int cur = (T_LEN & 1) * K_TAGS;
        float best = -3.4e38f;
        int tag = 0;
#pragma unroll
        for (int j = 0; j < K_TAGS; j++) {
            float s = fv[cur + j] + tr[j];
            if (s > best) { best = s; tag = j; }
        }
        out[0] = best;
        for (int t = T_LEN - 1; t >= 0; t--) {
            out[1 + t] = (float)tag;
            tag = bptr[t * K_TAGS + tag];
        }
    }
}

// ---------------- launch ----------------
extern "C" void kernel_launch(void* const* d_in, const int* in_sizes, int n_in,
                              void* d_out, int out_size) {
    const int*   sent   = (const int*)d_in[0];
    const float* E      = (const float*)d_in[1];
    const float* W_ih_f = (const float*)d_in[2];
    const float* W_hh_f = (const float*)d_in[3];
    const float* b_ih_f = (const float*)d_in[4];
    const float* b_hh_f = (const float*)d_in[5];
    const float* W_ih_b = (const float*)d_in[6];
    const float* W_hh_b = (const float*)d_in[7];
    const float* b_ih_b = (const float*)d_in[8];
    const float* b_hh_b = (const float*)d_in[9];
    const float* W_out  = (const float*)d_in[10];
    const float* b_out  = (const float*)d_in[11];
    const float* trans  = (const float*)d_in[12];
    float* out = (float*)d_out;

    cudaFuncSetAttribute(viterbi_kernel,
                         cudaFuncAttributeMaxDynamicSharedMemorySize, VIT_SMEM);

    gather_kernel<<<256, 256>>>(sent, E);

    dim3 ggrid(T_LEN / BM, G4 / BN, 2);
    xg_gemm_kernel<<<ggrid, 256>>>(W_ih_f, W_ih_b, b_ih_f, b_hh_f, b_ih_b, b_hh_b);

    // ---- LSTM: prefer 16-CTA non-portable cluster; fall back to 8-CTA ----
    bool did16 = false;
    {
        cudaError_t e = cudaFuncSetAttribute(
            lstm_kernel16, cudaFuncAttributeNonPortableClusterSizeAllowed, 1);
        if (e == cudaSuccess) {
            cudaLaunchConfig_t cfg = {};
            cfg.gridDim = dim3(16, 2, 1);
            cfg.blockDim = dim3(512, 1, 1);
            cfg.dynamicSmemBytes = 0;
            cfg.stream = 0;
            cudaLaunchAttribute attrs[1];
            attrs[0].id = cudaLaunchAttributeClusterDimension;
            attrs[0].val.clusterDim = {16, 1, 1};
            cfg.attrs = attrs;
            cfg.numAttrs = 1;
            int nclusters = 0;
            e = cudaOccupancyMaxActiveClusters(&nclusters, lstm_kernel16, &cfg);
            if (e == cudaSuccess && nclusters >= 1) {
                e = cudaLaunchKernelEx(&cfg, lstm_kernel16, W_hh_f, W_hh_b);
                if (e == cudaSuccess) did16 = true;
            }
        }
        if (!did16) {
            cudaGetLastError();  // clear any probe error
            lstm_kernel8<<<dim3(8, 2, 1), 512>>>(W_hh_f, W_hh_b);
        }
    }

    feats_gemm_kernel<<<T_LEN / FT_TT, 256>>>(W_out, b_out);

    viterbi_kernel<<<1, 64, VIT_SMEM>>>(trans, out);
}

// round 6
// speedup vs baseline: 1.3639x; 1.3639x over previous
#include <cuda_runtime.h>
#include <cstdint>
#include <math.h>

#define T_LEN  2048
#define D_EMB  300
#define H_DIM  256
#define G4     1024
#define K_TAGS 48
#define START_TAG 46
#define STOP_TAG  47

// ---------------- scratch (device globals; no allocation) ----------------
__device__ float g_x[T_LEN * D_EMB];        // gathered embeddings [T, D]
__device__ float g_xg[2][T_LEN * G4];       // input projections per dir [T, 4H]
__device__ float g_hs[2][T_LEN * H_DIM];    // hidden states per dir, time-aligned
__device__ float g_feats[T_LEN * K_TAGS];   // emission features [T, K]

// ---------------- f32x2 helpers ----------------
__device__ __forceinline__ unsigned long long pack2(float lo, float hi) {
    unsigned long long r;
    asm("mov.b64 %0, {%1,%2};" : "=l"(r) : "f"(lo), "f"(hi));
    return r;
}
__device__ __forceinline__ void unpack2(unsigned long long v, float& lo, float& hi) {
    asm("mov.b64 {%0,%1}, %2;" : "=f"(lo), "=f"(hi) : "l"(v));
}
__device__ __forceinline__ unsigned long long mul2(unsigned long long a, unsigned long long b) {
    unsigned long long d;
    asm("mul.rn.f32x2 %0, %1, %2;" : "=l"(d) : "l"(a), "l"(b));
    return d;
}
__device__ __forceinline__ unsigned long long fma2(unsigned long long a, unsigned long long b,
                                                   unsigned long long c) {
    unsigned long long d;
    asm("fma.rn.f32x2 %0, %1, %2, %3;" : "=l"(d) : "l"(a), "l"(b), "l"(c));
    return d;
}

// ---------------- 1) embedding gather ----------------
__global__ void gather_kernel(const int* __restrict__ sent,
                              const float* __restrict__ E) {
    int idx = blockIdx.x * blockDim.x + threadIdx.x;
    int total = T_LEN * D_EMB;
    for (; idx < total; idx += gridDim.x * blockDim.x) {
        int t = idx / D_EMB;
        int d = idx - t * D_EMB;
        long long row = sent[t];
        g_x[idx] = E[row * D_EMB + d];
    }
}

// ---------------- 2) xg GEMM: [T,D] @ [4H,D]^T + (b_ih + b_hh) ----------------
#define BM 64
#define BN 64
#define BK 12
__global__ void xg_gemm_kernel(const float* __restrict__ Wf,
                               const float* __restrict__ Wb,
                               const float* __restrict__ bihf,
                               const float* __restrict__ bhhf,
                               const float* __restrict__ bihb,
                               const float* __restrict__ bhhb) {
    int dir = blockIdx.z;
    const float* W  = dir ? Wb   : Wf;
    const float* b1 = dir ? bihb : bihf;
    const float* b2 = dir ? bhhb : bhhf;

    __shared__ float As[BK][BM];
    __shared__ float Bs[BK][BN];

    int t0 = blockIdx.x * BM;
    int r0 = blockIdx.y * BN;
    int tid = threadIdx.x;           // 256 threads
    int tx = tid & 15;
    int ty = tid >> 4;

    float acc[4][4];
#pragma unroll
    for (int i = 0; i < 4; i++)
#pragma unroll
        for (int j = 0; j < 4; j++) acc[i][j] = 0.f;

    for (int k0 = 0; k0 < D_EMB; k0 += BK) {   // 300 = 25 * 12, no guards
#pragma unroll
        for (int l2 = 0; l2 < 3; l2++) {
            int idx = tid + l2 * 256;       // 0..767
            int row = idx / 12;             // 0..63
            int kk  = idx - row * 12;
            int tg = t0 + row;
            int ts = dir ? (T_LEN - 1 - tg) : tg;
            As[kk][row] = g_x[ts * D_EMB + k0 + kk];
            Bs[kk][row] = W[(r0 + row) * D_EMB + k0 + kk];
        }
        __syncthreads();
#pragma unroll
        for (int kk = 0; kk < BK; kk++) {
            float ra[4], rb[4];
#pragma unroll
            for (int i = 0; i < 4; i++) ra[i] = As[kk][ty * 4 + i];
#pragma unroll
            for (int j = 0; j < 4; j++) rb[j] = Bs[kk][tx * 4 + j];
#pragma unroll
            for (int i = 0; i < 4; i++)
#pragma unroll
                for (int j = 0; j < 4; j++) acc[i][j] += ra[i] * rb[j];
        }
        __syncthreads();
    }

#pragma unroll
    for (int i = 0; i < 4; i++) {
        int t = t0 + ty * 4 + i;
#pragma unroll
        for (int j = 0; j < 4; j++) {
            int r = r0 + tx * 4 + j;
            g_xg[dir][t * G4 + r] = acc[i][j] + b1[r] + b2[r];
        }
    }
}

// ---------------- 3) LSTM recurrence: 8-CTA cluster per direction ----------------
// CTA rank owns hidden units [rank*32, rank*32+32). Warp w owns units 2w,2w+1
// (8 W rows). Lane l covers k-chunk [8l,8l+8) as f32x2. Per step:
//   16 fma2 partials -> 7-shfl reduce-scatter + realign + 2-shfl combine
//   (lane finalizes row l&7) -> branch-free activation -> 4-shfl gate gather
//   -> c/h update -> lanes 0-7 fan the packed h pair to all 8 CTAs in ONE
//   warp store instruction -> split cluster barrier (arrive, hs store, wait).
__global__ void __launch_bounds__(512, 1) __cluster_dims__(8, 1, 1)
lstm_kernel8(const float* __restrict__ Whf, const float* __restrict__ Whb) {
    __shared__ float h_buf[2][H_DIM];

    int dir = blockIdx.y;
    const float* Whh = dir ? Whb : Whf;
    const float* xg = g_xg[dir];
    float* hs = g_hs[dir];

    uint32_t rank;
    asm("mov.u32 %0, %%cluster_ctarank;" : "=r"(rank));

    int tid = threadIdx.x;
    int w = tid >> 5;
    int l = tid & 31;
    int r = l & 7;                 // W row this lane finalizes
    int gate = r & 3;
    int du = r >> 2;
    int xg_col = gate * H_DIM + (int)rank * 32 + 2 * w + du;

    unsigned long long w2[8][4];
#pragma unroll
    for (int q = 0; q < 8; q++) {
        int row = (q & 3) * H_DIM + (int)rank * 32 + 2 * w + (q >> 2);
        const float4* p = (const float4*)(Whh + (size_t)row * H_DIM + l * 8);
        float4 a = p[0];
        float4 b = p[1];
        w2[q][0] = pack2(a.x, a.y); w2[q][1] = pack2(a.z, a.w);
        w2[q][2] = pack2(b.x, b.y); w2[q][3] = pack2(b.z, b.w);
    }

    if (tid < 2 * H_DIM) ((float*)h_buf)[tid] = 0.f;
    uint32_t hb = (uint32_t)__cvta_generic_to_shared(&h_buf[0][0]);

    uint32_t rH[8];
#pragma unroll
    for (int tg = 0; tg < 8; tg++) {
        asm("mapa.shared::cluster.u32 %0, %1, %2;" : "=r"(rH[tg]) : "r"(hb), "r"(tg));
    }

    __syncthreads();
    asm volatile("barrier.cluster.arrive.aligned;" ::: "memory");
    asm volatile("barrier.cluster.wait.aligned;" ::: "memory");

    float c_reg = 0.f;
    float xg_pref = xg[xg_col];
    const float LOG2E = 1.4426950408889634f;

#pragma unroll 1
    for (int t = 0; t < T_LEN; t++) {
        int cur = t & 1;
        int nxt = cur ^ 1;

        float4 ha = *(const float4*)&h_buf[cur][l * 8];
        float4 hc = *(const float4*)&h_buf[cur][l * 8 + 4];
        unsigned long long h2[4] = { pack2(ha.x, ha.y), pack2(ha.z, ha.w),
                                     pack2(hc.x, hc.y), pack2(hc.z, hc.w) };
        float v[8];
#pragma unroll
        for (int q = 0; q < 8; q++) {
            unsigned long long acc = mul2(w2[q][0], h2[0]);
            acc = fma2(w2[q][1], h2[1], acc);
            acc = fma2(w2[q][2], h2[2], acc);
            acc = fma2(w2[q][3], h2[3], acc);
            float lo, hi;
            unpack2(acc, lo, hi);
            v[q] = lo + hi;
        }

        // reduce-scatter: row bit2 <- lane bit4, bit1 <- bit3, bit0 <- bit2
#pragma unroll
        for (int i = 0; i < 4; i++) {
            float send = (l & 16) ? v[i] : v[i + 4];
            float recv = __shfl_xor_sync(0xffffffffu, send, 16);
            float keep = (l & 16) ? v[i + 4] : v[i];
            v[i] = keep + recv;
        }
#pragma unroll
        for (int i = 0; i < 2; i++) {
            float send = (l & 8) ? v[i] : v[i + 2];
            float recv = __shfl_xor_sync(0xffffffffu, send, 8);
            float keep = (l & 8) ? v[i + 2] : v[i];
            v[i] = keep + recv;
        }
        {
            float send = (l & 4) ? v[0] : v[1];
            float recv = __shfl_xor_sync(0xffffffffu, send, 4);
            float keep = (l & 4) ? v[1] : v[0];
            v[0] = keep + recv;
        }
        // realign: lane l gets row (l&7), partial (l>>3)&3; combine 4 partials
        float x = __shfl_sync(0xffffffffu, v[0], ((l & 7) << 2) | ((l >> 3) & 3));
        x += __shfl_xor_sync(0xffffffffu, x, 8);
        x += __shfl_xor_sync(0xffffffffu, x, 16);

        float pre = x + xg_pref;
        if (t + 1 < T_LEN)
            xg_pref = xg[(size_t)(t + 1) * G4 + xg_col];

        // branch-free activation: gate 2 -> tanh, else sigmoid (EX2 + RCP)
        float aa = (gate == 2) ? (2.f * LOG2E) : (-LOG2E);
        float e = exp2f(aa * pre);
        float z = __fdividef(1.f, 1.f + e);
        float act = (gate == 2) ? fmaf(-2.f, z, 1.f) : z;

        // gather i,f,g,o from canonical lanes 0-7 (rows 0-7)
        int base = ((l >> 2) & 1) * 4;
        float iv = __shfl_sync(0xffffffffu, act, base);
        float fv = __shfl_sync(0xffffffffu, act, base + 1);
        float gg = __shfl_sync(0xffffffffu, act, base + 2);
        float ov = __shfl_sync(0xffffffffu, act, base + 3);

        c_reg = fmaf(fv, c_reg, iv * gg);
        float e2 = exp2f(2.f * LOG2E * c_reg);
        float hval = ov * fmaf(-2.f, __fdividef(1.f, 1.f + e2), 1.f);

        // all lanes obtain the warp's h pair; lanes 0-7 fan out (one instr)
        float h0 = __shfl_sync(0xffffffffu, hval, 0);
        float h1 = __shfl_sync(0xffffffffu, hval, 4);
        unsigned long long pk = pack2(h0, h1);
        uint32_t off = (uint32_t)((nxt * H_DIM + (int)rank * 32 + 2 * w) * 4);
        if (l < 8) {
            asm volatile("st.shared::cluster.b64 [%0], %1;"
                         :: "r"(rH[l] + off), "l"(pk) : "memory");
        }

        asm volatile("barrier.cluster.arrive.aligned;" ::: "memory");

        if (l == 0) {
            int tout = dir ? (T_LEN - 1 - t) : t;
            *(float2*)&hs[(size_t)tout * H_DIM + rank * 32 + 2 * w] =
                make_float2(h0, h1);
        }

        asm volatile("barrier.cluster.wait.aligned;" ::: "memory");
    }

    asm volatile("barrier.cluster.arrive.aligned;" ::: "memory");
    asm volatile("barrier.cluster.wait.aligned;" ::: "memory");
}

// ---------------- 4) feats GEMM: [T,512] @ [48,512]^T + b_out ----------------
#define FT_TT 64
__global__ void feats_gemm_kernel(const float* __restrict__ W_out,
                                  const float* __restrict__ b_out) {
    __shared__ float As[32][FT_TT];   // [j][t]
    __shared__ float Bs[32][K_TAGS];  // [j][k]

    int t0 = blockIdx.x * FT_TT;
    int tid = threadIdx.x;            // 256
    int tx = tid & 15;                // k-group: 3 tags
    int ty = tid >> 4;                // t-group: 4 steps

    float acc[4][3];
#pragma unroll
    for (int i = 0; i < 4; i++)
#pragma unroll
        for (int k = 0; k < 3; k++) acc[i][k] = 0.f;

    for (int j0 = 0; j0 < 2 * H_DIM; j0 += 32) {
#pragma unroll
        for (int i = 0; i < 8; i++) {
            int idx = tid + i * 256;        // 0..2047
            int jj = idx & 31;
            int tt = idx >> 5;
            int j = j0 + jj;
            float hv = (j < H_DIM)
                ? g_hs[0][(size_t)(t0 + tt) * H_DIM + j]
                : g_hs[1][(size_t)(t0 + tt) * H_DIM + (j - H_DIM)];
            As[jj][tt] = hv;
        }
#pragma unroll
        for (int i = 0; i < 6; i++) {
            int idx = tid + i * 256;        // 0..1535
            int k = idx % K_TAGS;
            int jj = idx / K_TAGS;
            Bs[jj][k] = W_out[(size_t)k * (2 * H_DIM) + j0 + jj];
        }
        __syncthreads();
#pragma unroll
        for (int jj = 0; jj < 32; jj++) {
            float a[4], b[3];
#pragma unroll
            for (int i = 0; i < 4; i++) a[i] = As[jj][ty * 4 + i];
#pragma unroll
            for (int k = 0; k < 3; k++) b[k] = Bs[jj][tx * 3 + k];
#pragma unroll
            for (int i = 0; i < 4; i++)
#pragma unroll
                for (int k = 0; k < 3; k++) acc[i][k] += a[i] * b[k];
        }
        __syncthreads();
    }

#pragma unroll
    for (int i = 0; i < 4; i++) {
        int t = t0 + ty * 4 + i;
#pragma unroll
        for (int k = 0; k < 3; k++) {
            int kk = tx * 3 + k;
            g_feats[t * K_TAGS + kk] = acc[i][k] + b_out[kk];
        }
    }
}

// ---------------- 5) Viterbi + backtrace (single CTA, 96 threads) ----------------
// Threads t and t+48 each scan 24 prev-tags for next-tag t (t+48 owns the
// upper range), combine via SMEM with exact first-index tie-breaking
// (low half owns smaller indices; upper half wins only on strict >).
#define VIT_SMEM (T_LEN * K_TAGS + 2 * K_TAGS * 4 + K_TAGS * 4 + K_TAGS * 4 + 16)
extern __shared__ unsigned char vit_smem[];
__global__ void viterbi_kernel(const float* __restrict__ trans,
                               float* __restrict__ out) {
    unsigned char* bptr = vit_smem;                          // [T][48] u8 = 96KB
    float* fv = (float*)(vit_smem + T_LEN * K_TAGS);         // [2][48]
    float* ps = fv + 2 * K_TAGS;                             // [48] hi-partial score
    int*   pa = (int*)(ps + K_TAGS);                         // [48] hi-partial arg
    int tid = threadIdx.x;  // 96
    int tag = (tid < K_TAGS) ? tid : (tid - K_TAGS);
    int jlo = (tid < K_TAGS) ? 0 : 24;                       // prev range start

    float tr[24];
#pragma unroll
    for (int j = 0; j < 24; j++) tr[j] = trans[tag * K_TAGS + jlo + j];
    if (tid < K_TAGS) fv[tid] = (tid == START_TAG) ? 0.f : -10000.f;
    float featp = g_feats[tag];
    __syncthreads();

    for (int t = 0; t < T_LEN; t++) {
        int cur = (t & 1) * K_TAGS;
        int nxt = K_TAGS - cur;

        // 4 independent max chains over this thread's 24 prev-tags
        float b0 = -3.4e38f, b1 = -3.4e38f, b2 = -3.4e38f, b3 = -3.4e38f;
        int a0 = 0, a1 = 1, a2 = 2, a3 = 3;
#pragma unroll
        for (int j = 0; j < 24; j += 4) {
            float s0 = fv[cur + jlo + j]     + tr[j];
            float s1 = fv[cur + jlo + j + 1] + tr[j + 1];
            float s2 = fv[cur + jlo + j + 2] + tr[j + 2];
            float s3 = fv[cur + jlo + j + 3] + tr[j + 3];
            if (s0 > b0) { b0 = s0; a0 = j; }
            if (s1 > b1) { b1 = s1; a1 = j + 1; }
            if (s2 > b2) { b2 = s2; a2 = j + 2; }
            if (s3 > b3) { b3 = s3; a3 = j + 3; }
        }
        float bv = b0; int ba = a0;
        if (b1 > bv || (b1 == bv && a1 < ba)) { bv = b1; ba = a1; }
        if (b2 > bv || (b2 == bv && a2 < ba)) { bv = b2; ba = a2; }
        if (b3 > bv || (b3 == bv && a3 < ba)) { bv = b3; ba = a3; }
        ba += jlo;

        if (tid >= K_TAGS) {           // upper half publishes its partial
            ps[tag] = bv;
            pa[tag] = ba;
        }
        __syncthreads();

        if (tid < K_TAGS) {
            float hv = ps[tag];
            // strict > : ties go to the low half (smaller indices) = jnp.argmax
            if (hv > bv) { bv = hv; ba = pa[tag]; }
            float feat = featp;
            if (t + 1 < T_LEN) featp = g_feats[(t + 1) * K_TAGS + tag];
            fv[nxt + tag] = bv + feat;
            bptr[t * K_TAGS + tag] = (unsigned char)ba;
        } else {
            if (t + 1 < T_LEN) featp = g_feats[(t + 1) * K_TAGS + tag];
        }
        __syncthreads();
    }

    if (tid == 0) {
        int cur = (T_LEN & 1) * K_TAGS;   // = 0 for even T
        float best = -3.4e38f;
        int btag = 0;
#pragma unroll
        for (int j = 0; j < K_TAGS; j++) {
            float s = fv[cur + j] + trans[STOP_TAG * K_TAGS + j];
            if (s > best) { best = s; btag = j; }
        }
        out[0] = best;
        for (int t = T_LEN - 1; t >= 0; t--) {
            out[1 + t] = (float)btag;
            btag = bptr[t * K_TAGS + btag];
        }
    }
}

// ---------------- launch ----------------
extern "C" void kernel_launch(void* const* d_in, const int* in_sizes, int n_in,
                              void* d_out, int out_size) {
    const int*   sent   = (const int*)d_in[0];
    const float* E      = (const float*)d_in[1];
    const float* W_ih_f = (const float*)d_in[2];
    const float* W_hh_f = (const float*)d_in[3];
    const float* b_ih_f = (const float*)d_in[4];
    const float* b_hh_f = (const float*)d_in[5];
    const float* W_ih_b = (const float*)d_in[6];
    const float* W_hh_b = (const float*)d_in[7];
    const float* b_ih_b = (const float*)d_in[8];
    const float* b_hh_b = (const float*)d_in[9];
    const float* W_out  = (const float*)d_in[10];
    const float* b_out  = (const float*)d_in[11];
    const float* trans  = (const float*)d_in[12];
    float* out = (float*)d_out;

    cudaFuncSetAttribute(viterbi_kernel,
                         cudaFuncAttributeMaxDynamicSharedMemorySize, VIT_SMEM);

    gather_kernel<<<256, 256>>>(sent, E);

    dim3 ggrid(T_LEN / BM, G4 / BN, 2);
    xg_gemm_kernel<<<ggrid, 256>>>(W_ih_f, W_ih_b, b_ih_f, b_hh_f, b_ih_b, b_hh_b);

    lstm_kernel8<<<dim3(8, 2, 1), 512>>>(W_hh_f, W_hh_b);

    feats_gemm_kernel<<<T_LEN / FT_TT, 256>>>(W_out, b_out);

    viterbi_kernel<<<1, 96, VIT_SMEM>>>(trans, out);
}